// round 9
// baseline (speedup 1.0000x reference)
#include <cuda_runtime.h>
#include <cstdint>

#define TWO_PI_F 6.283185307179586f
#define S_TOTAL 1024
#define Dm 96
#define Din 64
#define NBg 8
#define WELEM (Dm * Dm)          // 9216
#define CHUNK 128

typedef unsigned long long u64;

// Scratch: per-position weight matrices, layout W[s][j][i] (i contiguous)
__device__ float g_W1[(size_t)S_TOTAL * WELEM];
__device__ float g_W2[(size_t)S_TOTAL * WELEM];
// Pre-transposed static matrices: [k][i], i contiguous
__device__ float gM1T[Din * Dm];
__device__ float gWrT[Din * Dm];
__device__ float gM2T[Dm * Dm];

__device__ __forceinline__ u64 f2fma(u64 a, u64 b, u64 c) {
    u64 d; asm("fma.rn.f32x2 %0, %1, %2, %3;" : "=l"(d) : "l"(a), "l"(b), "l"(c)); return d;
}
__device__ __forceinline__ u64 f2add(u64 a, u64 b) {
    u64 d; asm("add.rn.f32x2 %0, %1, %2;" : "=l"(d) : "l"(a), "l"(b)); return d;
}
__device__ __forceinline__ u64 pk2(float lo, float hi) {
    u64 r; asm("mov.b64 %0, {%1, %2};" : "=l"(r) : "f"(lo), "f"(hi)); return r;
}
__device__ __forceinline__ void up2(u64 v, float& lo, float& hi) {
    asm("mov.b64 {%0, %1}, %2;" : "=f"(lo), "=f"(hi) : "l"(v));
}

__device__ __forceinline__ float warp_sum(float v) {
    v += __shfl_xor_sync(0xffffffffu, v, 16);
    v += __shfl_xor_sync(0xffffffffu, v, 8);
    v += __shfl_xor_sync(0xffffffffu, v, 4);
    v += __shfl_xor_sync(0xffffffffu, v, 2);
    v += __shfl_xor_sync(0xffffffffu, v, 1);
    return v;
}

// ---------------------------------------------------------------------------
// Kernel 1: W[s,i,j] = sum_g P[i,j,g]*cos(2*pi*s/T), T=(i*96+j)*8+g+2 via
// Chebyshev recurrence, packed f32x2 math. Also transposes M1/Wres1/M2.
// ---------------------------------------------------------------------------
__global__ void __launch_bounds__(256) precompute_W(
    const float* __restrict__ P1, const float* __restrict__ P2,
    const float* __restrict__ M1, const float* __restrict__ Wr,
    const float* __restrict__ M2)
{
    const int e = blockIdx.x * 256 + threadIdx.x;       // 0..9215

    if (blockIdx.y == 0 && blockIdx.z == 0) {
        if (e < Dm * Din) {
            int i = e / Din, k = e - i * Din;
            gM1T[k * Dm + i] = M1[e];
            gWrT[k * Dm + i] = Wr[e];
        }
        if (e < Dm * Dm) {
            int i = e / Dm, k = e - i * Dm;
            gM2T[k * Dm + i] = M2[e];
        }
    }

    const float* __restrict__ P = blockIdx.z ? P2 : P1;
    float* __restrict__ Wg = blockIdx.z ? g_W2 : g_W1;
    const int i = e % Dm;
    const int j = e / Dm;
    const int base = (i * Dm + j) * NBg;
    const int s0 = blockIdx.y * CHUNK;

    float c[NBg], q[NBg], a2[NBg];
#pragma unroll
    for (int g = 0; g < NBg; g++) {
        float T = (float)(base + g + 2);
        float invT = 1.0f / T;
        a2[g] = 2.0f * cosf(TWO_PI_F * invT);
        c[g]  = cosf(TWO_PI_F * (fmodf((float)s0, T) * invT));
        q[g]  = cosf(TWO_PI_F * (fmodf((float)(s0 - 1), T) * invT));
    }

    u64 C[4], N[4], A[4], Pp[4];
#pragma unroll
    for (int h = 0; h < 4; h++) {
        C[h]  = pk2(c[2*h], c[2*h+1]);
        N[h]  = pk2(-q[2*h], -q[2*h+1]);
        A[h]  = pk2(a2[2*h], a2[2*h+1]);
        Pp[h] = pk2(P[base + 2*h], P[base + 2*h + 1]);
    }

    float* __restrict__ outp = Wg + (size_t)s0 * WELEM + e;
#pragma unroll 4
    for (int s = 0; s < CHUNK; s++) {
        u64 acc0 = f2fma(Pp[0], C[0], f2fma(Pp[1], C[1], 0ULL));
        u64 acc1 = f2fma(Pp[2], C[2], f2fma(Pp[3], C[3], 0ULL));
        u64 t = f2add(acc0, acc1);
        float lo, hi; up2(t, lo, hi);
        outp[(size_t)s * WELEM] = lo + hi;
#pragma unroll
        for (int h = 0; h < 4; h++) {
            u64 cn = f2fma(A[h], C[h], N[h]);          // c_{s+1} = a2*c - c_{s-1}
            N[h] = C[h] ^ 0x8000000080000000ULL;       // -c_s   (ALU pipe)
            C[h] = cn;
        }
    }
}

// ---------------------------------------------------------------------------
// Kernel 2: fully fused, contraction-split. FOUR warps per position, each
// owning a j/k-QUARTER of every matmul; all 8 batches packed as 4 f32x2
// pairs (12 packed accumulators). W elements are loaded once chip-wide.
// Partial sums block-reduced via smem. Grid 1024 x 128 thr.
// ---------------------------------------------------------------------------
__global__ void __launch_bounds__(128) layers_kernel(
    const float* __restrict__ seq,
    const float* __restrict__ g1v, const float* __restrict__ b1v,
    const float* __restrict__ g2v, const float* __restrict__ b2v,
    float* __restrict__ out)
{
    __shared__ __align__(16) float xq[Din * 8];    // [k][b]
    __shared__ __align__(16) float buf[Dm * 8];    // [j][b] (xn1 / x1 / xn2)
    __shared__ u64 red[12][4][32];                 // reduction scratch

    const int w = threadIdx.x >> 5;
    const int lane = threadIdx.x & 31;
    const int s = blockIdx.x;
    const int i0 = lane, i1 = lane + 32, i2 = lane + 64;

    // ---- stage x[k][b] cooperatively ----
    for (int t = threadIdx.x; t < Din * 8; t += 128) {
        int k = t >> 3, b = t & 7;
        xq[k * 8 + b] = seq[((size_t)b * S_TOTAL + s) * Din + k];
    }
    __syncthreads();

    const float G1[3] = {g1v[i0], g1v[i1], g1v[i2]};
    const float B1[3] = {b1v[i0], b1v[i1], b1v[i2]};
    const float G2[3] = {g2v[i0], g2v[i1], g2v[i2]};
    const float B2[3] = {b2v[i0], b2v[i1], b2v[i2]};

    // block-wide reduce of 12 packed accumulators across the 4 warps
    auto reduce12 = [&](u64 (&acc)[12]) {
#pragma unroll
        for (int q = 0; q < 12; q++) red[q][w][lane] = acc[q];
        __syncthreads();
#pragma unroll
        for (int q = 0; q < 12; q++) {
            u64 a = f2add(acc[q], red[q][w ^ 1][lane]);
            u64 b = f2add(red[q][w ^ 2][lane], red[q][w ^ 3][lane]);
            acc[q] = f2add(a, b);
        }
        __syncthreads();
    };

    // ---- phase 1 (k-quarter): xt = M1 x, rsa = Wres1 x (partials) ----
    u64 xta[12], x1a[12];                       // x1a starts as rsa partial
#pragma unroll
    for (int q = 0; q < 12; q++) { xta[q] = 0ULL; x1a[q] = 0ULL; }
    {
        const int k0 = w * 16;
#pragma unroll 4
        for (int k = k0; k < k0 + 16; k++) {
            const float* mr = gM1T + k * Dm;
            const float* rr = gWrT + k * Dm;
            float m0 = mr[i0], m1 = mr[i1], m2 = mr[i2];
            float r0 = rr[i0], r1 = rr[i1], r2 = rr[i2];
            u64 M0 = pk2(m0, m0), M1p = pk2(m1, m1), M2p = pk2(m2, m2);
            u64 R0 = pk2(r0, r0), R1p = pk2(r1, r1), R2p = pk2(r2, r2);
            const u64* xp = (const u64*)(xq + k * 8);
#pragma unroll
            for (int p = 0; p < 4; p++) {
                u64 x = xp[p];
                xta[p*3+0] = f2fma(M0,  x, xta[p*3+0]);
                xta[p*3+1] = f2fma(M1p, x, xta[p*3+1]);
                xta[p*3+2] = f2fma(M2p, x, xta[p*3+2]);
                x1a[p*3+0] = f2fma(R0,  x, x1a[p*3+0]);
                x1a[p*3+1] = f2fma(R1p, x, x1a[p*3+1]);
                x1a[p*3+2] = f2fma(R2p, x, x1a[p*3+2]);
            }
        }
    }
    reduce12(xta);                              // xta now FULL in every warp

    // ---- LN1: warp w handles batches {2w, 2w+1} (= pack index p = w) ----
    {
        float a[2][3], xn[2][3];
#pragma unroll
        for (int t = 0; t < 3; t++) up2(xta[w*3+t], a[0][t], a[1][t]);
#pragma unroll
        for (int bb = 0; bb < 2; bb++) {
            float mu = warp_sum(a[bb][0] + a[bb][1] + a[bb][2]) * (1.0f/96.0f);
            float d0 = a[bb][0]-mu, d1 = a[bb][1]-mu, d2 = a[bb][2]-mu;
            float var = warp_sum(d0*d0 + d1*d1 + d2*d2) * (1.0f/96.0f);
            float rq = rsqrtf(var + 1e-5f);
            xn[bb][0] = fmaf(d0*rq, G1[0], B1[0]);
            xn[bb][1] = fmaf(d1*rq, G1[1], B1[1]);
            xn[bb][2] = fmaf(d2*rq, G1[2], B1[2]);
        }
        int bA = 2 * w;
#pragma unroll
        for (int bb = 0; bb < 2; bb++) {
            buf[i0*8 + bA+bb] = xn[bb][0];
            buf[i1*8 + bA+bb] = xn[bb][1];
            buf[i2*8 + bA+bb] = xn[bb][2];
        }
    }
    __syncthreads();

    // ---- W1 (j-quarter): x1a += W1[s,:,j-quarter] @ xn1 ----
    {
        const float* __restrict__ Wr = g_W1 + (size_t)s * WELEM;
        const int j0 = w * 24;
#pragma unroll 4
        for (int j = j0; j < j0 + 24; j++) {
            float w0 = Wr[j*Dm + i0], w1 = Wr[j*Dm + i1], w2 = Wr[j*Dm + i2];
            u64 W0 = pk2(w0, w0), W1p = pk2(w1, w1), W2p = pk2(w2, w2);
            const u64* xp = (const u64*)(buf + j * 8);
#pragma unroll
            for (int p = 0; p < 4; p++) {
                u64 x = xp[p];
                x1a[p*3+0] = f2fma(W0,  x, x1a[p*3+0]);
                x1a[p*3+1] = f2fma(W1p, x, x1a[p*3+1]);
                x1a[p*3+2] = f2fma(W2p, x, x1a[p*3+2]);
            }
        }
    }
    reduce12(x1a);                              // x1 FULL in every warp

    // ---- write x1 -> buf (warp w writes its 2 batches) ----
    {
        float v[2][3];
#pragma unroll
        for (int t = 0; t < 3; t++) up2(x1a[w*3+t], v[0][t], v[1][t]);
        int bA = 2 * w;
#pragma unroll
        for (int bb = 0; bb < 2; bb++) {
            buf[i0*8 + bA+bb] = v[bb][0];
            buf[i1*8 + bA+bb] = v[bb][1];
            buf[i2*8 + bA+bb] = v[bb][2];
        }
    }
    __syncthreads();

    // ---- M2 (k-quarter): t2a = M2[:, k-quarter] @ x1 ----
    u64 t2a[12];
#pragma unroll
    for (int q = 0; q < 12; q++) t2a[q] = 0ULL;
    {
        const int k0 = w * 24;
#pragma unroll 4
        for (int k = k0; k < k0 + 24; k++) {
            const float* mr = gM2T + k * Dm;
            float m0 = mr[i0], m1 = mr[i1], m2 = mr[i2];
            u64 M0 = pk2(m0, m0), M1p = pk2(m1, m1), M2p = pk2(m2, m2);
            const u64* xp = (const u64*)(buf + k * 8);
#pragma unroll
            for (int p = 0; p < 4; p++) {
                u64 x = xp[p];
                t2a[p*3+0] = f2fma(M0,  x, t2a[p*3+0]);
                t2a[p*3+1] = f2fma(M1p, x, t2a[p*3+1]);
                t2a[p*3+2] = f2fma(M2p, x, t2a[p*3+2]);
            }
        }
    }
    reduce12(t2a);

    // ---- LN2 -> buf ----
    {
        float a[2][3], xn[2][3];
#pragma unroll
        for (int t = 0; t < 3; t++) up2(t2a[w*3+t], a[0][t], a[1][t]);
#pragma unroll
        for (int bb = 0; bb < 2; bb++) {
            float mu = warp_sum(a[bb][0] + a[bb][1] + a[bb][2]) * (1.0f/96.0f);
            float d0 = a[bb][0]-mu, d1 = a[bb][1]-mu, d2 = a[bb][2]-mu;
            float var = warp_sum(d0*d0 + d1*d1 + d2*d2) * (1.0f/96.0f);
            float rq = rsqrtf(var + 1e-5f);
            xn[bb][0] = fmaf(d0*rq, G2[0], B2[0]);
            xn[bb][1] = fmaf(d1*rq, G2[1], B2[1]);
            xn[bb][2] = fmaf(d2*rq, G2[2], B2[2]);
        }
        int bA = 2 * w;
#pragma unroll
        for (int bb = 0; bb < 2; bb++) {
            buf[i0*8 + bA+bb] = xn[bb][0];
            buf[i1*8 + bA+bb] = xn[bb][1];
            buf[i2*8 + bA+bb] = xn[bb][2];
        }
    }
    __syncthreads();

    // ---- W2 (j-quarter): oa = W2[s,:,j-quarter] @ xn2 ----
    u64 oa[12];
#pragma unroll
    for (int q = 0; q < 12; q++) oa[q] = 0ULL;
    {
        const float* __restrict__ Wr = g_W2 + (size_t)s * WELEM;
        const int j0 = w * 24;
#pragma unroll 4
        for (int j = j0; j < j0 + 24; j++) {
            float w0 = Wr[j*Dm + i0], w1 = Wr[j*Dm + i1], w2 = Wr[j*Dm + i2];
            u64 W0 = pk2(w0, w0), W1p = pk2(w1, w1), W2p = pk2(w2, w2);
            const u64* xp = (const u64*)(buf + j * 8);
#pragma unroll
            for (int p = 0; p < 4; p++) {
                u64 x = xp[p];
                oa[p*3+0] = f2fma(W0,  x, oa[p*3+0]);
                oa[p*3+1] = f2fma(W1p, x, oa[p*3+1]);
                oa[p*3+2] = f2fma(W2p, x, oa[p*3+2]);
            }
        }
    }
    reduce12(oa);

    // ---- epilogue: out = oa + x1 (warp w stores its 2 batches) ----
    {
        float v[2][3];
#pragma unroll
        for (int t = 0; t < 3; t++) {
            u64 r = f2add(oa[w*3+t], x1a[w*3+t]);
            up2(r, v[0][t], v[1][t]);
        }
        int bA = 2 * w;
#pragma unroll
        for (int bb = 0; bb < 2; bb++) {
            float* op = out + ((size_t)(bA+bb) * S_TOTAL + s) * Dm;
            op[i0] = v[bb][0];
            op[i1] = v[bb][1];
            op[i2] = v[bb][2];
        }
    }
}

extern "C" void kernel_launch(void* const* d_in, const int* in_sizes, int n_in,
                              void* d_out, int out_size) {
    const float* seq = (const float*)d_in[0];
    const float* M1  = (const float*)d_in[1];
    const float* P1  = (const float*)d_in[2];
    const float* Wr1 = (const float*)d_in[3];
    const float* g1  = (const float*)d_in[4];
    const float* b1  = (const float*)d_in[5];
    const float* M2  = (const float*)d_in[6];
    const float* P2  = (const float*)d_in[7];
    const float* g2  = (const float*)d_in[8];
    const float* b2  = (const float*)d_in[9];
    float* out = (float*)d_out;

    precompute_W<<<dim3(WELEM / 256, S_TOTAL / CHUNK, 2), 256>>>(P1, P2, M1, Wr1, M2);
    layers_kernel<<<S_TOTAL, 128>>>(seq, g1, b1, g2, b2, out);
}

// round 10
// speedup vs baseline: 1.0244x; 1.0244x over previous
#include <cuda_runtime.h>
#include <cuda_fp16.h>
#include <cstdint>

#define TWO_PI_F 6.283185307179586f
#define S_TOTAL 1024
#define Dm 96
#define Din 64
#define NBg 8
#define WELEM (Dm * Dm)          // 9216
#define JP 48                    // j-pairs
#define CHUNK 128

typedef unsigned long long u64;
typedef unsigned int u32;

// Per-position weight matrices in fp16, layout [s][jp][i], half2 = (j=2jp, j=2jp+1)
__device__ __half2 g_W1h[(size_t)S_TOTAL * JP * Dm];
__device__ __half2 g_W2h[(size_t)S_TOTAL * JP * Dm];
// Pre-transposed static matrices: [k][i], i contiguous
__device__ float gM1T[Din * Dm];
__device__ float gWrT[Din * Dm];
__device__ float gM2T[Dm * Dm];

__device__ __forceinline__ u64 f2fma(u64 a, u64 b, u64 c) {
    u64 d; asm("fma.rn.f32x2 %0, %1, %2, %3;" : "=l"(d) : "l"(a), "l"(b), "l"(c)); return d;
}
__device__ __forceinline__ u64 f2add(u64 a, u64 b) {
    u64 d; asm("add.rn.f32x2 %0, %1, %2;" : "=l"(d) : "l"(a), "l"(b)); return d;
}
__device__ __forceinline__ u64 pk2(float lo, float hi) {
    u64 r; asm("mov.b64 %0, {%1, %2};" : "=l"(r) : "f"(lo), "f"(hi)); return r;
}
__device__ __forceinline__ void up2(u64 v, float& lo, float& hi) {
    asm("mov.b64 {%0, %1}, %2;" : "=f"(lo), "=f"(hi) : "l"(v));
}

__device__ __forceinline__ float warp_sum(float v) {
    v += __shfl_xor_sync(0xffffffffu, v, 16);
    v += __shfl_xor_sync(0xffffffffu, v, 8);
    v += __shfl_xor_sync(0xffffffffu, v, 4);
    v += __shfl_xor_sync(0xffffffffu, v, 2);
    v += __shfl_xor_sync(0xffffffffu, v, 1);
    return v;
}

// ---------------------------------------------------------------------------
// Kernel 1: W[s,i,j] = sum_g P[i,j,g]*cos(2*pi*s/T), T=(i*96+j)*8+g+2.
// One thread owns a j-PAIR (16 consecutive periods), runs 2 Chebyshev
// recurrences, emits one coalesced half2 store per s.
// grid: (18, 8, 2), block 256.  Also transposes M1/Wres1/M2.
// ---------------------------------------------------------------------------
__global__ void __launch_bounds__(256) precompute_W(
    const float* __restrict__ P1, const float* __restrict__ P2,
    const float* __restrict__ M1, const float* __restrict__ Wr,
    const float* __restrict__ M2)
{
    const int e = blockIdx.x * 256 + threadIdx.x;       // 0..4607
    if (e >= Dm * JP) return;

    if (blockIdx.y == 0) {
        int te = blockIdx.z * 4608 + e;                 // 0..9215
        if (te < Dm * Din) {
            int i = te / Din, k = te - i * Din;
            gM1T[k * Dm + i] = M1[te];
            gWrT[k * Dm + i] = Wr[te];
        }
        if (te < Dm * Dm) {
            int i = te / Dm, k = te - i * Dm;
            gM2T[k * Dm + i] = M2[te];
        }
    }

    const float* __restrict__ P = blockIdx.z ? P2 : P1;
    __half2* __restrict__ Wg = blockIdx.z ? g_W2h : g_W1h;
    const int i  = e % Dm;
    const int jp = e / Dm;                              // 0..47
    const int base = (i * Dm + 2 * jp) * NBg;           // 16 consecutive periods
    const int s0 = blockIdx.y * CHUNK;

    float c[16], q[16], a2[16];
#pragma unroll
    for (int t = 0; t < 16; t++) {
        float T = (float)(base + t + 2);
        float invT = 1.0f / T;
        a2[t] = 2.0f * cosf(TWO_PI_F * invT);
        c[t]  = cosf(TWO_PI_F * (fmodf((float)s0, T) * invT));
        q[t]  = cosf(TWO_PI_F * (fmodf((float)(s0 - 1), T) * invT));
    }

    u64 C[8], N[8], A[8], Pp[8];
#pragma unroll
    for (int h = 0; h < 8; h++) {
        C[h]  = pk2(c[2*h], c[2*h+1]);
        N[h]  = pk2(-q[2*h], -q[2*h+1]);
        A[h]  = pk2(a2[2*h], a2[2*h+1]);
        Pp[h] = pk2(P[base + 2*h], P[base + 2*h + 1]);
    }

    __half2* __restrict__ outp = Wg + (size_t)s0 * (JP * Dm) + jp * Dm + i;
#pragma unroll 4
    for (int s = 0; s < CHUNK; s++) {
        // j0 = 2jp uses h=0..3, j1 uses h=4..7
        u64 accA = f2fma(Pp[0], C[0], f2fma(Pp[1], C[1], 0ULL));
        accA = f2fma(Pp[2], C[2], f2fma(Pp[3], C[3], accA));
        u64 accB = f2fma(Pp[4], C[4], f2fma(Pp[5], C[5], 0ULL));
        accB = f2fma(Pp[6], C[6], f2fma(Pp[7], C[7], accB));
        float la, ha, lb, hb;
        up2(accA, la, ha);
        up2(accB, lb, hb);
        outp[(size_t)s * (JP * Dm)] = __floats2half2_rn(la + ha, lb + hb);
#pragma unroll
        for (int h = 0; h < 8; h++) {
            u64 cn = f2fma(A[h], C[h], N[h]);          // c_{s+1} = a2*c - c_{s-1}
            N[h] = C[h] ^ 0x8000000080000000ULL;       // -c_s   (ALU pipe)
            C[h] = cn;
        }
    }
}

// ---------------------------------------------------------------------------
// Kernel 2: fully fused, contraction-split, fp16 W. FOUR warps per position,
// each owning a j/k-QUARTER of every matmul; all 8 batches packed as 4 f32x2
// pairs (12 packed accumulators). W loaded once chip-wide as half2 (1 LDG.32
// covers 2 j's). Partials block-reduced via smem. Grid 1024 x 128 thr.
// ---------------------------------------------------------------------------
__global__ void __launch_bounds__(128) layers_kernel(
    const float* __restrict__ seq,
    const float* __restrict__ g1v, const float* __restrict__ b1v,
    const float* __restrict__ g2v, const float* __restrict__ b2v,
    float* __restrict__ out)
{
    __shared__ __align__(16) float xq[Din * 8];    // [k][b]
    __shared__ __align__(16) float buf[Dm * 8];    // [j][b] (xn1 / x1 / xn2)
    __shared__ u64 red[12][4][32];                 // reduction scratch

    const int w = threadIdx.x >> 5;
    const int lane = threadIdx.x & 31;
    const int s = blockIdx.x;
    const int i0 = lane, i1 = lane + 32, i2 = lane + 64;

    // ---- stage x[k][b] cooperatively ----
    for (int t = threadIdx.x; t < Din * 8; t += 128) {
        int k = t >> 3, b = t & 7;
        xq[k * 8 + b] = seq[((size_t)b * S_TOTAL + s) * Din + k];
    }
    __syncthreads();

    const float G1[3] = {g1v[i0], g1v[i1], g1v[i2]};
    const float B1[3] = {b1v[i0], b1v[i1], b1v[i2]};
    const float G2[3] = {g2v[i0], g2v[i1], g2v[i2]};
    const float B2[3] = {b2v[i0], b2v[i1], b2v[i2]};

    auto reduce12 = [&](u64 (&acc)[12]) {
#pragma unroll
        for (int q = 0; q < 12; q++) red[q][w][lane] = acc[q];
        __syncthreads();
#pragma unroll
        for (int q = 0; q < 12; q++) {
            u64 a = f2add(acc[q], red[q][w ^ 1][lane]);
            u64 b = f2add(red[q][w ^ 2][lane], red[q][w ^ 3][lane]);
            acc[q] = f2add(a, b);
        }
        __syncthreads();
    };

    // W-stage inner: process j-pair quarter from half2 matrix into 12 accs
    auto wmat = [&](const __half2* __restrict__ Wh, u64 (&acc)[12]) {
        const int jp0 = w * 12;
#pragma unroll 4
        for (int jp = jp0; jp < jp0 + 12; jp++) {
            __half2 q0 = Wh[jp * Dm + i0];
            __half2 q1 = Wh[jp * Dm + i1];
            __half2 q2 = Wh[jp * Dm + i2];
            float2 f0 = __half22float2(q0);
            float2 f1 = __half22float2(q1);
            float2 f2 = __half22float2(q2);
            u64 A0 = pk2(f0.x, f0.x), A1 = pk2(f1.x, f1.x), A2 = pk2(f2.x, f2.x);
            u64 Bb0 = pk2(f0.y, f0.y), Bb1 = pk2(f1.y, f1.y), Bb2 = pk2(f2.y, f2.y);
            const u64* xa = (const u64*)(buf + (2 * jp) * 8);
            const u64* xb = (const u64*)(buf + (2 * jp + 1) * 8);
#pragma unroll
            for (int p = 0; p < 4; p++) {
                u64 x = xa[p];
                acc[p*3+0] = f2fma(A0, x, acc[p*3+0]);
                acc[p*3+1] = f2fma(A1, x, acc[p*3+1]);
                acc[p*3+2] = f2fma(A2, x, acc[p*3+2]);
            }
#pragma unroll
            for (int p = 0; p < 4; p++) {
                u64 x = xb[p];
                acc[p*3+0] = f2fma(Bb0, x, acc[p*3+0]);
                acc[p*3+1] = f2fma(Bb1, x, acc[p*3+1]);
                acc[p*3+2] = f2fma(Bb2, x, acc[p*3+2]);
            }
        }
    };

    // ---- phase 1 (k-quarter): xt = M1 x, res = Wres1 x (partials) ----
    u64 xta[12], x1a[12];                       // x1a starts as res partial
#pragma unroll
    for (int q = 0; q < 12; q++) { xta[q] = 0ULL; x1a[q] = 0ULL; }
    {
        const int k0 = w * 16;
#pragma unroll 4
        for (int k = k0; k < k0 + 16; k++) {
            const float* mr = gM1T + k * Dm;
            const float* rr = gWrT + k * Dm;
            float m0 = mr[i0], m1 = mr[i1], m2 = mr[i2];
            float r0 = rr[i0], r1 = rr[i1], r2 = rr[i2];
            u64 M0 = pk2(m0, m0), M1p = pk2(m1, m1), M2p = pk2(m2, m2);
            u64 R0 = pk2(r0, r0), R1p = pk2(r1, r1), R2p = pk2(r2, r2);
            const u64* xp = (const u64*)(xq + k * 8);
#pragma unroll
            for (int p = 0; p < 4; p++) {
                u64 x = xp[p];
                xta[p*3+0] = f2fma(M0,  x, xta[p*3+0]);
                xta[p*3+1] = f2fma(M1p, x, xta[p*3+1]);
                xta[p*3+2] = f2fma(M2p, x, xta[p*3+2]);
                x1a[p*3+0] = f2fma(R0,  x, x1a[p*3+0]);
                x1a[p*3+1] = f2fma(R1p, x, x1a[p*3+1]);
                x1a[p*3+2] = f2fma(R2p, x, x1a[p*3+2]);
            }
        }
    }
    reduce12(xta);

    // ---- LN1: warp w handles batches {2w, 2w+1} (pack index p = w) ----
    {
        float a[2][3], xn[2][3];
#pragma unroll
        for (int t = 0; t < 3; t++) up2(xta[w*3+t], a[0][t], a[1][t]);
#pragma unroll
        for (int bb = 0; bb < 2; bb++) {
            float mu = warp_sum(a[bb][0] + a[bb][1] + a[bb][2]) * (1.0f/96.0f);
            float d0 = a[bb][0]-mu, d1 = a[bb][1]-mu, d2 = a[bb][2]-mu;
            float var = warp_sum(d0*d0 + d1*d1 + d2*d2) * (1.0f/96.0f);
            float rq = rsqrtf(var + 1e-5f);
            xn[bb][0] = fmaf(d0*rq, G1[0], B1[0]);
            xn[bb][1] = fmaf(d1*rq, G1[1], B1[1]);
            xn[bb][2] = fmaf(d2*rq, G1[2], B1[2]);
        }
        int bA = 2 * w;
#pragma unroll
        for (int bb = 0; bb < 2; bb++) {
            buf[i0*8 + bA+bb] = xn[bb][0];
            buf[i1*8 + bA+bb] = xn[bb][1];
            buf[i2*8 + bA+bb] = xn[bb][2];
        }
    }
    __syncthreads();

    // ---- W1 (j-quarter): x1a += W1[s] partial ----
    wmat(g_W1h + (size_t)s * (JP * Dm), x1a);
    reduce12(x1a);                              // x1 FULL in every warp

    // ---- write x1 -> buf ----
    {
        float v[2][3];
#pragma unroll
        for (int t = 0; t < 3; t++) up2(x1a[w*3+t], v[0][t], v[1][t]);
        int bA = 2 * w;
#pragma unroll
        for (int bb = 0; bb < 2; bb++) {
            buf[i0*8 + bA+bb] = v[bb][0];
            buf[i1*8 + bA+bb] = v[bb][1];
            buf[i2*8 + bA+bb] = v[bb][2];
        }
    }
    __syncthreads();

    // ---- M2 (k-quarter): t2a = M2 x1 partial ----
    u64 t2a[12];
#pragma unroll
    for (int q = 0; q < 12; q++) t2a[q] = 0ULL;
    {
        const int k0 = w * 24;
#pragma unroll 4
        for (int k = k0; k < k0 + 24; k++) {
            const float* mr = gM2T + k * Dm;
            float m0 = mr[i0], m1 = mr[i1], m2 = mr[i2];
            u64 M0 = pk2(m0, m0), M1p = pk2(m1, m1), M2p = pk2(m2, m2);
            const u64* xp = (const u64*)(buf + k * 8);
#pragma unroll
            for (int p = 0; p < 4; p++) {
                u64 x = xp[p];
                t2a[p*3+0] = f2fma(M0,  x, t2a[p*3+0]);
                t2a[p*3+1] = f2fma(M1p, x, t2a[p*3+1]);
                t2a[p*3+2] = f2fma(M2p, x, t2a[p*3+2]);
            }
        }
    }
    reduce12(t2a);

    // ---- LN2 -> buf ----
    {
        float a[2][3], xn[2][3];
#pragma unroll
        for (int t = 0; t < 3; t++) up2(t2a[w*3+t], a[0][t], a[1][t]);
#pragma unroll
        for (int bb = 0; bb < 2; bb++) {
            float mu = warp_sum(a[bb][0] + a[bb][1] + a[bb][2]) * (1.0f/96.0f);
            float d0 = a[bb][0]-mu, d1 = a[bb][1]-mu, d2 = a[bb][2]-mu;
            float var = warp_sum(d0*d0 + d1*d1 + d2*d2) * (1.0f/96.0f);
            float rq = rsqrtf(var + 1e-5f);
            xn[bb][0] = fmaf(d0*rq, G2[0], B2[0]);
            xn[bb][1] = fmaf(d1*rq, G2[1], B2[1]);
            xn[bb][2] = fmaf(d2*rq, G2[2], B2[2]);
        }
        int bA = 2 * w;
#pragma unroll
        for (int bb = 0; bb < 2; bb++) {
            buf[i0*8 + bA+bb] = xn[bb][0];
            buf[i1*8 + bA+bb] = xn[bb][1];
            buf[i2*8 + bA+bb] = xn[bb][2];
        }
    }
    __syncthreads();

    // ---- W2 (j-quarter): oa = W2[s] partial ----
    u64 oa[12];
#pragma unroll
    for (int q = 0; q < 12; q++) oa[q] = 0ULL;
    wmat(g_W2h + (size_t)s * (JP * Dm), oa);
    reduce12(oa);

    // ---- epilogue: out = oa + x1 ----
    {
        float v[2][3];
#pragma unroll
        for (int t = 0; t < 3; t++) {
            u64 r = f2add(oa[w*3+t], x1a[w*3+t]);
            up2(r, v[0][t], v[1][t]);
        }
        int bA = 2 * w;
#pragma unroll
        for (int bb = 0; bb < 2; bb++) {
            float* op = out + ((size_t)(bA+bb) * S_TOTAL + s) * Dm;
            op[i0] = v[bb][0];
            op[i1] = v[bb][1];
            op[i2] = v[bb][2];
        }
    }
}

extern "C" void kernel_launch(void* const* d_in, const int* in_sizes, int n_in,
                              void* d_out, int out_size) {
    const float* seq = (const float*)d_in[0];
    const float* M1  = (const float*)d_in[1];
    const float* P1  = (const float*)d_in[2];
    const float* Wr1 = (const float*)d_in[3];
    const float* g1  = (const float*)d_in[4];
    const float* b1  = (const float*)d_in[5];
    const float* M2  = (const float*)d_in[6];
    const float* P2  = (const float*)d_in[7];
    const float* g2  = (const float*)d_in[8];
    const float* b2  = (const float*)d_in[9];
    float* out = (float*)d_out;

    precompute_W<<<dim3(18, S_TOTAL / CHUNK, 2), 256>>>(P1, P2, M1, Wr1, M2);
    layers_kernel<<<S_TOTAL, 128>>>(seq, g1, b1, g2, b2, out);
}

// round 14
// speedup vs baseline: 1.0557x; 1.0305x over previous
#include <cuda_runtime.h>
#include <cuda_fp16.h>
#include <cstdint>

#define TWO_PI_F 6.283185307179586f
#define S_TOTAL 1024
#define Dm 96
#define Din 64
#define NBg 8
#define JP 48                    // j-pairs
#define CHUNK 128

typedef unsigned long long u64;

// Per-position weight matrices in fp16, layout [s][jp][i], half2 = (j=2jp, j=2jp+1)
__device__ __half2 g_W1h[(size_t)S_TOTAL * JP * Dm];
__device__ __half2 g_W2h[(size_t)S_TOTAL * JP * Dm];
// Pre-transposed static matrices: [k][i], i contiguous
__device__ float gM1T[Din * Dm];
__device__ float gWrT[Din * Dm];
__device__ float gM2T[Dm * Dm];

__device__ __forceinline__ u64 f2fma(u64 a, u64 b, u64 c) {
    u64 d; asm("fma.rn.f32x2 %0, %1, %2, %3;" : "=l"(d) : "l"(a), "l"(b), "l"(c)); return d;
}
__device__ __forceinline__ u64 f2add(u64 a, u64 b) {
    u64 d; asm("add.rn.f32x2 %0, %1, %2;" : "=l"(d) : "l"(a), "l"(b)); return d;
}
__device__ __forceinline__ u64 pk2(float lo, float hi) {
    u64 r; asm("mov.b64 %0, {%1, %2};" : "=l"(r) : "f"(lo), "f"(hi)); return r;
}
__device__ __forceinline__ void up2(u64 v, float& lo, float& hi) {
    asm("mov.b64 {%0, %1}, %2;" : "=f"(lo), "=f"(hi) : "l"(v));
}
__device__ __forceinline__ void cp_async16(void* dst, const void* src) {
    unsigned d = (unsigned)__cvta_generic_to_shared(dst);
    asm volatile("cp.async.cg.shared.global [%0], [%1], 16;\n" :: "r"(d), "l"(src));
}

__device__ __forceinline__ float warp_sum(float v) {
    v += __shfl_xor_sync(0xffffffffu, v, 16);
    v += __shfl_xor_sync(0xffffffffu, v, 8);
    v += __shfl_xor_sync(0xffffffffu, v, 4);
    v += __shfl_xor_sync(0xffffffffu, v, 2);
    v += __shfl_xor_sync(0xffffffffu, v, 1);
    return v;
}

// ---------------------------------------------------------------------------
// Kernel 1: W[s,i,j] = sum_g P[i,j,g]*cos(2*pi*s/T), T=(i*96+j)*8+g+2.
// One thread owns a j-PAIR (16 consecutive periods), runs 2 Chebyshev
// recurrences with ACCURATE cosf seeds (fast-seed phase error ~eps/sin(theta)
// exceeds 1e-3 for large T — measured in R11), emits one coalesced half2
// store per s. grid: (18, 8, 2), block 256. Also transposes M1/Wres1/M2.
// ---------------------------------------------------------------------------
__global__ void __launch_bounds__(256) precompute_W(
    const float* __restrict__ P1, const float* __restrict__ P2,
    const float* __restrict__ M1, const float* __restrict__ Wr,
    const float* __restrict__ M2)
{
    const int e = blockIdx.x * 256 + threadIdx.x;       // 0..4607
    if (e >= Dm * JP) return;

    if (blockIdx.y == 0) {
        int te = blockIdx.z * 4608 + e;                 // 0..9215
        if (te < Dm * Din) {
            int i = te / Din, k = te - i * Din;
            gM1T[k * Dm + i] = M1[te];
            gWrT[k * Dm + i] = Wr[te];
        }
        if (te < Dm * Dm) {
            int i = te / Dm, k = te - i * Dm;
            gM2T[k * Dm + i] = M2[te];
        }
    }

    const float* __restrict__ P = blockIdx.z ? P2 : P1;
    __half2* __restrict__ Wg = blockIdx.z ? g_W2h : g_W1h;
    const int i  = e % Dm;
    const int jp = e / Dm;                              // 0..47
    const int base = (i * Dm + 2 * jp) * NBg;           // 16 consecutive periods
    const int s0 = blockIdx.y * CHUNK;

    float c[16], q[16], a2[16];
#pragma unroll
    for (int t = 0; t < 16; t++) {
        float T = (float)(base + t + 2);
        float invT = 1.0f / T;
        a2[t] = 2.0f * cosf(TWO_PI_F * invT);
        c[t]  = cosf(TWO_PI_F * (fmodf((float)s0, T) * invT));
        q[t]  = cosf(TWO_PI_F * (fmodf((float)(s0 - 1), T) * invT));
    }

    u64 C[8], N[8], A[8], Pp[8];
#pragma unroll
    for (int h = 0; h < 8; h++) {
        C[h]  = pk2(c[2*h], c[2*h+1]);
        N[h]  = pk2(-q[2*h], -q[2*h+1]);
        A[h]  = pk2(a2[2*h], a2[2*h+1]);
        Pp[h] = pk2(P[base + 2*h], P[base + 2*h + 1]);
    }

    __half2* __restrict__ outp = Wg + (size_t)s0 * (JP * Dm) + jp * Dm + i;
#pragma unroll 4
    for (int s = 0; s < CHUNK; s++) {
        u64 accA = f2fma(Pp[0], C[0], f2fma(Pp[1], C[1], 0ULL));
        accA = f2fma(Pp[2], C[2], f2fma(Pp[3], C[3], accA));
        u64 accB = f2fma(Pp[4], C[4], f2fma(Pp[5], C[5], 0ULL));
        accB = f2fma(Pp[6], C[6], f2fma(Pp[7], C[7], accB));
        float la, ha, lb, hb;
        up2(accA, la, ha);
        up2(accB, lb, hb);
        outp[(size_t)s * (JP * Dm)] = __floats2half2_rn(la + ha, lb + hb);
#pragma unroll
        for (int h = 0; h < 8; h++) {
            u64 cn = f2fma(A[h], C[h], N[h]);          // c_{s+1} = a2*c - c_{s-1}
            N[h] = C[h] ^ 0x8000000080000000ULL;       // -c_s   (ALU pipe)
            C[h] = cn;
        }
    }
}

// ---------------------------------------------------------------------------
// Kernel 2: fully fused, contraction-split, fp16 W prefetched to SMEM via
// cp.async. FOUR warps per position, j/k-quarter split, 8 batches as 4 f32x2
// pairs (12 packed accumulators). W tiles land in smem while phase-1 runs;
// W matmuls read conflict-free LDS.32. Grid (512,2) x 128 thr, ~53KB dyn smem.
// ---------------------------------------------------------------------------
__global__ void __launch_bounds__(128) layers_kernel(
    const float* __restrict__ seq,
    const float* __restrict__ g1v, const float* __restrict__ b1v,
    const float* __restrict__ g2v, const float* __restrict__ b2v,
    float* __restrict__ out)
{
    extern __shared__ __align__(16) char smraw[];
    __half2* sW1 = (__half2*)smraw;                    // 4608 half2 = 18432B
    __half2* sW2 = sW1 + JP * Dm;                      // 18432B
    u64*   red   = (u64*)(sW2 + JP * Dm);              // 12 x 4 x 32 u64 = 12288B
    float* xq    = (float*)(red + 12 * 4 * 32);        // 512 f = 2048B
    float* buf   = xq + Din * 8;                       // 768 f = 3072B

    const int w = threadIdx.x >> 5;
    const int lane = threadIdx.x & 31;
    const int s = blockIdx.y * (S_TOTAL / 2) + blockIdx.x;
    const int i0 = lane, i1 = lane + 32, i2 = lane + 64;

    // ---- prefetch W1 then W2 tiles (1152 x 16B each, 128 threads) ----
    {
        const char* src1 = (const char*)(g_W1h + (size_t)s * (JP * Dm));
        const char* src2 = (const char*)(g_W2h + (size_t)s * (JP * Dm));
        for (int off = threadIdx.x * 16; off < JP * Dm * 4; off += 128 * 16)
            cp_async16((char*)sW1 + off, src1 + off);
        asm volatile("cp.async.commit_group;\n");
        for (int off = threadIdx.x * 16; off < JP * Dm * 4; off += 128 * 16)
            cp_async16((char*)sW2 + off, src2 + off);
        asm volatile("cp.async.commit_group;\n");
    }

    // ---- stage x[k][b] cooperatively ----
    for (int t = threadIdx.x; t < Din * 8; t += 128) {
        int k = t >> 3, b = t & 7;
        xq[k * 8 + b] = seq[((size_t)b * S_TOTAL + s) * Din + k];
    }
    __syncthreads();

    const float G1[3] = {g1v[i0], g1v[i1], g1v[i2]};
    const float B1[3] = {b1v[i0], b1v[i1], b1v[i2]};
    const float G2[3] = {g2v[i0], g2v[i1], g2v[i2]};
    const float B2[3] = {b2v[i0], b2v[i1], b2v[i2]};

    auto reduce12 = [&](u64 (&acc)[12]) {
#pragma unroll
        for (int q = 0; q < 12; q++) red[(q * 4 + w) * 32 + lane] = acc[q];
        __syncthreads();
#pragma unroll
        for (int q = 0; q < 12; q++) {
            u64 a = f2add(acc[q], red[(q * 4 + (w ^ 1)) * 32 + lane]);
            u64 b = f2add(red[(q * 4 + (w ^ 2)) * 32 + lane], red[(q * 4 + (w ^ 3)) * 32 + lane]);
            acc[q] = f2add(a, b);
        }
        __syncthreads();
    };

    // W-stage inner: j-pair quarter from half2 smem tile into 12 accs
    auto wmat = [&](const __half2* __restrict__ Wh, u64 (&acc)[12]) {
        const int jp0 = w * 12;
#pragma unroll 4
        for (int jp = jp0; jp < jp0 + 12; jp++) {
            __half2 q0 = Wh[jp * Dm + i0];
            __half2 q1 = Wh[jp * Dm + i1];
            __half2 q2 = Wh[jp * Dm + i2];
            float2 f0 = __half22float2(q0);
            float2 f1 = __half22float2(q1);
            float2 f2 = __half22float2(q2);
            u64 A0 = pk2(f0.x, f0.x), A1 = pk2(f1.x, f1.x), A2 = pk2(f2.x, f2.x);
            u64 Bb0 = pk2(f0.y, f0.y), Bb1 = pk2(f1.y, f1.y), Bb2 = pk2(f2.y, f2.y);
            const u64* xa = (const u64*)(buf + (2 * jp) * 8);
            const u64* xb = (const u64*)(buf + (2 * jp + 1) * 8);
#pragma unroll
            for (int p = 0; p < 4; p++) {
                u64 x = xa[p];
                acc[p*3+0] = f2fma(A0, x, acc[p*3+0]);
                acc[p*3+1] = f2fma(A1, x, acc[p*3+1]);
                acc[p*3+2] = f2fma(A2, x, acc[p*3+2]);
            }
#pragma unroll
            for (int p = 0; p < 4; p++) {
                u64 x = xb[p];
                acc[p*3+0] = f2fma(Bb0, x, acc[p*3+0]);
                acc[p*3+1] = f2fma(Bb1, x, acc[p*3+1]);
                acc[p*3+2] = f2fma(Bb2, x, acc[p*3+2]);
            }
        }
    };

    // ---- phase 1 (k-quarter): xt = M1 x, res = Wres1 x (partials) ----
    u64 xta[12], x1a[12];                       // x1a starts as res partial
#pragma unroll
    for (int q = 0; q < 12; q++) { xta[q] = 0ULL; x1a[q] = 0ULL; }
    {
        const int k0 = w * 16;
#pragma unroll 4
        for (int k = k0; k < k0 + 16; k++) {
            const float* mr = gM1T + k * Dm;
            const float* rr = gWrT + k * Dm;
            float m0 = mr[i0], m1 = mr[i1], m2 = mr[i2];
            float r0 = rr[i0], r1 = rr[i1], r2 = rr[i2];
            u64 M0 = pk2(m0, m0), M1p = pk2(m1, m1), M2p = pk2(m2, m2);
            u64 R0 = pk2(r0, r0), R1p = pk2(r1, r1), R2p = pk2(r2, r2);
            const u64* xp = (const u64*)(xq + k * 8);
#pragma unroll
            for (int p = 0; p < 4; p++) {
                u64 x = xp[p];
                xta[p*3+0] = f2fma(M0,  x, xta[p*3+0]);
                xta[p*3+1] = f2fma(M1p, x, xta[p*3+1]);
                xta[p*3+2] = f2fma(M2p, x, xta[p*3+2]);
                x1a[p*3+0] = f2fma(R0,  x, x1a[p*3+0]);
                x1a[p*3+1] = f2fma(R1p, x, x1a[p*3+1]);
                x1a[p*3+2] = f2fma(R2p, x, x1a[p*3+2]);
            }
        }
    }
    reduce12(xta);

    // ---- LN1: warp w handles batches {2w, 2w+1} (pack index p = w) ----
    {
        float a[2][3], xn[2][3];
#pragma unroll
        for (int t = 0; t < 3; t++) up2(xta[w*3+t], a[0][t], a[1][t]);
#pragma unroll
        for (int bb = 0; bb < 2; bb++) {
            float mu = warp_sum(a[bb][0] + a[bb][1] + a[bb][2]) * (1.0f/96.0f);
            float d0 = a[bb][0]-mu, d1 = a[bb][1]-mu, d2 = a[bb][2]-mu;
            float var = warp_sum(d0*d0 + d1*d1 + d2*d2) * (1.0f/96.0f);
            float rq = rsqrtf(var + 1e-5f);
            xn[bb][0] = fmaf(d0*rq, G1[0], B1[0]);
            xn[bb][1] = fmaf(d1*rq, G1[1], B1[1]);
            xn[bb][2] = fmaf(d2*rq, G1[2], B1[2]);
        }
        int bA = 2 * w;
#pragma unroll
        for (int bb = 0; bb < 2; bb++) {
            buf[i0*8 + bA+bb] = xn[bb][0];
            buf[i1*8 + bA+bb] = xn[bb][1];
            buf[i2*8 + bA+bb] = xn[bb][2];
        }
    }
    asm volatile("cp.async.wait_group 1;\n");   // W1 tile resident
    __syncthreads();

    // ---- W1 (j-quarter, from smem): x1a += partial ----
    wmat(sW1, x1a);
    reduce12(x1a);                              // x1 FULL in every warp

    // ---- write x1 -> buf ----
    {
        float v[2][3];
#pragma unroll
        for (int t = 0; t < 3; t++) up2(x1a[w*3+t], v[0][t], v[1][t]);
        int bA = 2 * w;
#pragma unroll
        for (int bb = 0; bb < 2; bb++) {
            buf[i0*8 + bA+bb] = v[bb][0];
            buf[i1*8 + bA+bb] = v[bb][1];
            buf[i2*8 + bA+bb] = v[bb][2];
        }
    }
    asm volatile("cp.async.wait_group 0;\n");   // W2 tile resident
    __syncthreads();

    // ---- M2 (k-quarter): t2a = M2 x1 partial ----
    u64 t2a[12];
#pragma unroll
    for (int q = 0; q < 12; q++) t2a[q] = 0ULL;
    {
        const int k0 = w * 24;
#pragma unroll 4
        for (int k = k0; k < k0 + 24; k++) {
            const float* mr = gM2T + k * Dm;
            float m0 = mr[i0], m1 = mr[i1], m2 = mr[i2];
            u64 M0 = pk2(m0, m0), M1p = pk2(m1, m1), M2p = pk2(m2, m2);
            const u64* xp = (const u64*)(buf + k * 8);
#pragma unroll
            for (int p = 0; p < 4; p++) {
                u64 x = xp[p];
                t2a[p*3+0] = f2fma(M0,  x, t2a[p*3+0]);
                t2a[p*3+1] = f2fma(M1p, x, t2a[p*3+1]);
                t2a[p*3+2] = f2fma(M2p, x, t2a[p*3+2]);
            }
        }
    }
    reduce12(t2a);

    // ---- LN2 -> buf ----
    {
        float a[2][3], xn[2][3];
#pragma unroll
        for (int t = 0; t < 3; t++) up2(t2a[w*3+t], a[0][t], a[1][t]);
#pragma unroll
        for (int bb = 0; bb < 2; bb++) {
            float mu = warp_sum(a[bb][0] + a[bb][1] + a[bb][2]) * (1.0f/96.0f);
            float d0 = a[bb][0]-mu, d1 = a[bb][1]-mu, d2 = a[bb][2]-mu;
            float var = warp_sum(d0*d0 + d1*d1 + d2*d2) * (1.0f/96.0f);
            float rq = rsqrtf(var + 1e-5f);
            xn[bb][0] = fmaf(d0*rq, G2[0], B2[0]);
            xn[bb][1] = fmaf(d1*rq, G2[1], B2[1]);
            xn[bb][2] = fmaf(d2*rq, G2[2], B2[2]);
        }
        int bA = 2 * w;
#pragma unroll
        for (int bb = 0; bb < 2; bb++) {
            buf[i0*8 + bA+bb] = xn[bb][0];
            buf[i1*8 + bA+bb] = xn[bb][1];
            buf[i2*8 + bA+bb] = xn[bb][2];
        }
    }
    __syncthreads();

    // ---- W2 (j-quarter, from smem): oa partial ----
    u64 oa[12];
#pragma unroll
    for (int q = 0; q < 12; q++) oa[q] = 0ULL;
    wmat(sW2, oa);
    reduce12(oa);

    // ---- epilogue: out = oa + x1 ----
    {
        float v[2][3];
#pragma unroll
        for (int t = 0; t < 3; t++) {
            u64 r = f2add(oa[w*3+t], x1a[w*3+t]);
            up2(r, v[0][t], v[1][t]);
        }
        int bA = 2 * w;
#pragma unroll
        for (int bb = 0; bb < 2; bb++) {
            float* op = out + ((size_t)(bA+bb) * S_TOTAL + s) * Dm;
            op[i0] = v[bb][0];
            op[i1] = v[bb][1];
            op[i2] = v[bb][2];
        }
    }
}

#define LAYERS_SMEM (2 * JP * Dm * 4 + 12 * 4 * 32 * 8 + Din * 8 * 4 + Dm * 8 * 4)

extern "C" void kernel_launch(void* const* d_in, const int* in_sizes, int n_in,
                              void* d_out, int out_size) {
    const float* seq = (const float*)d_in[0];
    const float* M1  = (const float*)d_in[1];
    const float* P1  = (const float*)d_in[2];
    const float* Wr1 = (const float*)d_in[3];
    const float* g1  = (const float*)d_in[4];
    const float* b1  = (const float*)d_in[5];
    const float* M2  = (const float*)d_in[6];
    const float* P2  = (const float*)d_in[7];
    const float* g2  = (const float*)d_in[8];
    const float* b2  = (const float*)d_in[9];
    float* out = (float*)d_out;

    cudaFuncSetAttribute(layers_kernel,
                         cudaFuncAttributeMaxDynamicSharedMemorySize, LAYERS_SMEM);

    precompute_W<<<dim3(18, S_TOTAL / CHUNK, 2), 256>>>(P1, P2, M1, Wr1, M2);
    layers_kernel<<<dim3(S_TOTAL / 2, 2), 128, LAYERS_SMEM>>>(seq, g1, b1, g2, b2, out);
}

// round 16
// speedup vs baseline: 1.1255x; 1.0661x over previous
#include <cuda_runtime.h>
#include <cuda_fp16.h>
#include <cstdint>

#define TWO_PI_F 6.283185307179586f
#define S_TOTAL 1024
#define Dm 96
#define Din 64
#define NBg 8
#define JP 48                    // j-pairs
#define CHUNK 256

typedef unsigned long long u64;

// Per-position weight matrices in fp16, layout [s][jp][i], half2 = (j=2jp, j=2jp+1)
__device__ __half2 g_W1h[(size_t)S_TOTAL * JP * Dm];
__device__ __half2 g_W2h[(size_t)S_TOTAL * JP * Dm];
// Pre-transposed static matrices: [k][i], i contiguous
__device__ float gM1T[Din * Dm];
__device__ float gWrT[Din * Dm];
__device__ float gM2T[Dm * Dm];

__device__ __forceinline__ u64 f2fma(u64 a, u64 b, u64 c) {
    u64 d; asm("fma.rn.f32x2 %0, %1, %2, %3;" : "=l"(d) : "l"(a), "l"(b), "l"(c)); return d;
}
__device__ __forceinline__ u64 f2add(u64 a, u64 b) {
    u64 d; asm("add.rn.f32x2 %0, %1, %2;" : "=l"(d) : "l"(a), "l"(b)); return d;
}
__device__ __forceinline__ u64 pk2(float lo, float hi) {
    u64 r; asm("mov.b64 %0, {%1, %2};" : "=l"(r) : "f"(lo), "f"(hi)); return r;
}
__device__ __forceinline__ void up2(u64 v, float& lo, float& hi) {
    asm("mov.b64 {%0, %1}, %2;" : "=f"(lo), "=f"(hi) : "l"(v));
}
__device__ __forceinline__ void cp_async16(void* dst, const void* src) {
    unsigned d = (unsigned)__cvta_generic_to_shared(dst);
    asm volatile("cp.async.cg.shared.global [%0], [%1], 16;\n" :: "r"(d), "l"(src));
}

__device__ __forceinline__ float warp_sum(float v) {
    v += __shfl_xor_sync(0xffffffffu, v, 16);
    v += __shfl_xor_sync(0xffffffffu, v, 8);
    v += __shfl_xor_sync(0xffffffffu, v, 4);
    v += __shfl_xor_sync(0xffffffffu, v, 2);
    v += __shfl_xor_sync(0xffffffffu, v, 1);
    return v;
}

// ---------------------------------------------------------------------------
// Kernel 1: W[s,i,j] = sum_g P[i,j,g]*cos(2*pi*s/T), T=(i*96+j)*8+g+2.
// One thread owns a j-PAIR (16 consecutive periods), 2 Chebyshev recurrences,
// ACCURATE cosf seeds (fast seeds fail: phase error eps/sin(theta), R11).
// CHUNK=256 halves thread count -> setup cosf cost halves.
// grid: (18, 4, 2), block 256. Also transposes M1/Wres1/M2.
// ---------------------------------------------------------------------------
__global__ void __launch_bounds__(256) precompute_W(
    const float* __restrict__ P1, const float* __restrict__ P2,
    const float* __restrict__ M1, const float* __restrict__ Wr,
    const float* __restrict__ M2)
{
    const int e = blockIdx.x * 256 + threadIdx.x;       // 0..4607
    if (e >= Dm * JP) return;

    if (blockIdx.y == 0) {
        int te = blockIdx.z * 4608 + e;                 // 0..9215
        if (te < Dm * Din) {
            int i = te / Din, k = te - i * Din;
            gM1T[k * Dm + i] = M1[te];
            gWrT[k * Dm + i] = Wr[te];
        }
        if (te < Dm * Dm) {
            int i = te / Dm, k = te - i * Dm;
            gM2T[k * Dm + i] = M2[te];
        }
    }

    const float* __restrict__ P = blockIdx.z ? P2 : P1;
    __half2* __restrict__ Wg = blockIdx.z ? g_W2h : g_W1h;
    const int i  = e % Dm;
    const int jp = e / Dm;                              // 0..47
    const int base = (i * Dm + 2 * jp) * NBg;           // 16 consecutive periods
    const int s0 = blockIdx.y * CHUNK;

    float c[16], q[16], a2[16];
#pragma unroll
    for (int t = 0; t < 16; t++) {
        float T = (float)(base + t + 2);
        float invT = 1.0f / T;
        a2[t] = 2.0f * cosf(TWO_PI_F * invT);
        c[t]  = cosf(TWO_PI_F * (fmodf((float)s0, T) * invT));
        q[t]  = cosf(TWO_PI_F * (fmodf((float)(s0 - 1), T) * invT));
    }

    u64 C[8], N[8], A[8], Pp[8];
#pragma unroll
    for (int h = 0; h < 8; h++) {
        C[h]  = pk2(c[2*h], c[2*h+1]);
        N[h]  = pk2(-q[2*h], -q[2*h+1]);
        A[h]  = pk2(a2[2*h], a2[2*h+1]);
        Pp[h] = pk2(P[base + 2*h], P[base + 2*h + 1]);
    }

    __half2* __restrict__ outp = Wg + (size_t)s0 * (JP * Dm) + jp * Dm + i;
#pragma unroll 4
    for (int s = 0; s < CHUNK; s++) {
        u64 accA = f2fma(Pp[0], C[0], f2fma(Pp[1], C[1], 0ULL));
        accA = f2fma(Pp[2], C[2], f2fma(Pp[3], C[3], accA));
        u64 accB = f2fma(Pp[4], C[4], f2fma(Pp[5], C[5], 0ULL));
        accB = f2fma(Pp[6], C[6], f2fma(Pp[7], C[7], accB));
        float la, ha, lb, hb;
        up2(accA, la, ha);
        up2(accB, lb, hb);
        outp[(size_t)s * (JP * Dm)] = __floats2half2_rn(la + ha, lb + hb);
#pragma unroll
        for (int h = 0; h < 8; h++) {
            u64 cn = f2fma(A[h], C[h], N[h]);          // c_{s+1} = a2*c - c_{s-1}
            N[h] = C[h] ^ 0x8000000080000000ULL;       // -c_s   (ALU pipe)
            C[h] = cn;
        }
    }
}

// ---------------------------------------------------------------------------
// Kernel 2: fully fused, contraction-split, fp16 W via cp.async smem tiles.
// FOUR warps per position, j/k-quarter split, 8 batches as 4 f32x2 pairs.
// Reductions deliver ONLY pack p==w per warp (all consumers are pack-w).
// x broadcast loads are LDS.128 (ulonglong2). Grid (512,2) x 128 thr.
// ---------------------------------------------------------------------------
__global__ void __launch_bounds__(128) layers_kernel(
    const float* __restrict__ seq,
    const float* __restrict__ g1v, const float* __restrict__ b1v,
    const float* __restrict__ g2v, const float* __restrict__ b2v,
    float* __restrict__ out)
{
    extern __shared__ __align__(16) char smraw[];
    __half2* sW1 = (__half2*)smraw;                    // 18432B
    __half2* sW2 = sW1 + JP * Dm;                      // 18432B
    u64*   red   = (u64*)(sW2 + JP * Dm);              // 12288B
    float* xq    = (float*)(red + 12 * 4 * 32);        // 2048B
    float* buf   = xq + Din * 8;                       // 3072B

    const int w = threadIdx.x >> 5;
    const int lane = threadIdx.x & 31;
    const int s = blockIdx.y * (S_TOTAL / 2) + blockIdx.x;
    const int i0 = lane, i1 = lane + 32, i2 = lane + 64;

    // ---- prefetch W1 then W2 tiles ----
    {
        const char* src1 = (const char*)(g_W1h + (size_t)s * (JP * Dm));
        const char* src2 = (const char*)(g_W2h + (size_t)s * (JP * Dm));
        for (int off = threadIdx.x * 16; off < JP * Dm * 4; off += 128 * 16)
            cp_async16((char*)sW1 + off, src1 + off);
        asm volatile("cp.async.commit_group;\n");
        for (int off = threadIdx.x * 16; off < JP * Dm * 4; off += 128 * 16)
            cp_async16((char*)sW2 + off, src2 + off);
        asm volatile("cp.async.commit_group;\n");
    }

    // ---- stage x[k][b] cooperatively ----
    for (int t = threadIdx.x; t < Din * 8; t += 128) {
        int k = t >> 3, b = t & 7;
        xq[k * 8 + b] = seq[((size_t)b * S_TOTAL + s) * Din + k];
    }
    __syncthreads();

    const float G1[3] = {g1v[i0], g1v[i1], g1v[i2]};
    const float B1[3] = {b1v[i0], b1v[i1], b1v[i2]};
    const float G2[3] = {g2v[i0], g2v[i1], g2v[i2]};
    const float B2[3] = {b2v[i0], b2v[i1], b2v[i2]};

    // Reduce: each warp stores its 12 partials; reads back ONLY pack p==w
    // (accs 3w..3w+2) fully reduced. Other packs left as partials (unused).
    auto reduceW = [&](u64 (&acc)[12]) {
#pragma unroll
        for (int q = 0; q < 12; q++) red[(q * 4 + w) * 32 + lane] = acc[q];
        __syncthreads();
#pragma unroll
        for (int t = 0; t < 3; t++) {
            int q = w * 3 + t;
            u64 a = f2add(acc[q], red[(q * 4 + (w ^ 1)) * 32 + lane]);
            u64 b = f2add(red[(q * 4 + (w ^ 2)) * 32 + lane], red[(q * 4 + (w ^ 3)) * 32 + lane]);
            acc[q] = f2add(a, b);
        }
        __syncthreads();
    };

    // W-stage inner: j-pair quarter from half2 smem tile into 12 accs
    auto wmat = [&](const __half2* __restrict__ Wh, u64 (&acc)[12]) {
        const int jp0 = w * 12;
#pragma unroll 4
        for (int jp = jp0; jp < jp0 + 12; jp++) {
            __half2 q0 = Wh[jp * Dm + i0];
            __half2 q1 = Wh[jp * Dm + i1];
            __half2 q2 = Wh[jp * Dm + i2];
            float2 f0 = __half22float2(q0);
            float2 f1 = __half22float2(q1);
            float2 f2 = __half22float2(q2);
            u64 A0 = pk2(f0.x, f0.x), A1 = pk2(f1.x, f1.x), A2 = pk2(f2.x, f2.x);
            u64 Bb0 = pk2(f0.y, f0.y), Bb1 = pk2(f1.y, f1.y), Bb2 = pk2(f2.y, f2.y);
            ulonglong2 a01 = *(const ulonglong2*)(buf + (2 * jp) * 8);
            ulonglong2 a23 = *(const ulonglong2*)(buf + (2 * jp) * 8 + 4);
            ulonglong2 b01 = *(const ulonglong2*)(buf + (2 * jp + 1) * 8);
            ulonglong2 b23 = *(const ulonglong2*)(buf + (2 * jp + 1) * 8 + 4);
            acc[0]  = f2fma(A0, a01.x, acc[0]);
            acc[1]  = f2fma(A1, a01.x, acc[1]);
            acc[2]  = f2fma(A2, a01.x, acc[2]);
            acc[3]  = f2fma(A0, a01.y, acc[3]);
            acc[4]  = f2fma(A1, a01.y, acc[4]);
            acc[5]  = f2fma(A2, a01.y, acc[5]);
            acc[6]  = f2fma(A0, a23.x, acc[6]);
            acc[7]  = f2fma(A1, a23.x, acc[7]);
            acc[8]  = f2fma(A2, a23.x, acc[8]);
            acc[9]  = f2fma(A0, a23.y, acc[9]);
            acc[10] = f2fma(A1, a23.y, acc[10]);
            acc[11] = f2fma(A2, a23.y, acc[11]);
            acc[0]  = f2fma(Bb0, b01.x, acc[0]);
            acc[1]  = f2fma(Bb1, b01.x, acc[1]);
            acc[2]  = f2fma(Bb2, b01.x, acc[2]);
            acc[3]  = f2fma(Bb0, b01.y, acc[3]);
            acc[4]  = f2fma(Bb1, b01.y, acc[4]);
            acc[5]  = f2fma(Bb2, b01.y, acc[5]);
            acc[6]  = f2fma(Bb0, b23.x, acc[6]);
            acc[7]  = f2fma(Bb1, b23.x, acc[7]);
            acc[8]  = f2fma(Bb2, b23.x, acc[8]);
            acc[9]  = f2fma(Bb0, b23.y, acc[9]);
            acc[10] = f2fma(Bb1, b23.y, acc[10]);
            acc[11] = f2fma(Bb2, b23.y, acc[11]);
        }
    };

    // ---- phase 1 (k-quarter): xt = M1 x, res = Wres1 x (partials) ----
    u64 xta[12], x1a[12];                       // x1a starts as res partial
#pragma unroll
    for (int q = 0; q < 12; q++) { xta[q] = 0ULL; x1a[q] = 0ULL; }
    {
        const int k0 = w * 16;
#pragma unroll 4
        for (int k = k0; k < k0 + 16; k++) {
            const float* mr = gM1T + k * Dm;
            const float* rr = gWrT + k * Dm;
            float m0 = mr[i0], m1 = mr[i1], m2 = mr[i2];
            float r0 = rr[i0], r1 = rr[i1], r2 = rr[i2];
            u64 M0 = pk2(m0, m0), M1p = pk2(m1, m1), M2p = pk2(m2, m2);
            u64 R0 = pk2(r0, r0), R1p = pk2(r1, r1), R2p = pk2(r2, r2);
            ulonglong2 x01 = *(const ulonglong2*)(xq + k * 8);
            ulonglong2 x23 = *(const ulonglong2*)(xq + k * 8 + 4);
            u64 xs[4] = {x01.x, x01.y, x23.x, x23.y};
#pragma unroll
            for (int p = 0; p < 4; p++) {
                u64 x = xs[p];
                xta[p*3+0] = f2fma(M0,  x, xta[p*3+0]);
                xta[p*3+1] = f2fma(M1p, x, xta[p*3+1]);
                xta[p*3+2] = f2fma(M2p, x, xta[p*3+2]);
                x1a[p*3+0] = f2fma(R0,  x, x1a[p*3+0]);
                x1a[p*3+1] = f2fma(R1p, x, x1a[p*3+1]);
                x1a[p*3+2] = f2fma(R2p, x, x1a[p*3+2]);
            }
        }
    }
    reduceW(xta);                               // pack w now FULL

    // ---- LN1: warp w handles batches {2w, 2w+1} (pack index p = w) ----
    {
        float a[2][3], xn[2][3];
#pragma unroll
        for (int t = 0; t < 3; t++) up2(xta[w*3+t], a[0][t], a[1][t]);
#pragma unroll
        for (int bb = 0; bb < 2; bb++) {
            float mu = warp_sum(a[bb][0] + a[bb][1] + a[bb][2]) * (1.0f/96.0f);
            float d0 = a[bb][0]-mu, d1 = a[bb][1]-mu, d2 = a[bb][2]-mu;
            float var = warp_sum(d0*d0 + d1*d1 + d2*d2) * (1.0f/96.0f);
            float rq = rsqrtf(var + 1e-5f);
            xn[bb][0] = fmaf(d0*rq, G1[0], B1[0]);
            xn[bb][1] = fmaf(d1*rq, G1[1], B1[1]);
            xn[bb][2] = fmaf(d2*rq, G1[2], B1[2]);
        }
        int bA = 2 * w;
#pragma unroll
        for (int bb = 0; bb < 2; bb++) {
            buf[i0*8 + bA+bb] = xn[bb][0];
            buf[i1*8 + bA+bb] = xn[bb][1];
            buf[i2*8 + bA+bb] = xn[bb][2];
        }
    }
    asm volatile("cp.async.wait_group 1;\n");   // W1 tile resident
    __syncthreads();

    // ---- W1 (j-quarter, from smem): x1a += partial ----
    wmat(sW1, x1a);
    reduceW(x1a);                               // pack w FULL

    // ---- write x1 -> buf (warp w writes its 2 batches) ----
    {
        float v[2][3];
#pragma unroll
        for (int t = 0; t < 3; t++) up2(x1a[w*3+t], v[0][t], v[1][t]);
        int bA = 2 * w;
#pragma unroll
        for (int bb = 0; bb < 2; bb++) {
            buf[i0*8 + bA+bb] = v[bb][0];
            buf[i1*8 + bA+bb] = v[bb][1];
            buf[i2*8 + bA+bb] = v[bb][2];
        }
    }
    asm volatile("cp.async.wait_group 0;\n");   // W2 tile resident
    __syncthreads();

    // ---- M2 (k-quarter): t2a = M2 x1 partial ----
    u64 t2a[12];
#pragma unroll
    for (int q = 0; q < 12; q++) t2a[q] = 0ULL;
    {
        const int k0 = w * 24;
#pragma unroll 4
        for (int k = k0; k < k0 + 24; k++) {
            const float* mr = gM2T + k * Dm;
            float m0 = mr[i0], m1 = mr[i1], m2 = mr[i2];
            u64 M0 = pk2(m0, m0), M1p = pk2(m1, m1), M2p = pk2(m2, m2);
            ulonglong2 x01 = *(const ulonglong2*)(buf + k * 8);
            ulonglong2 x23 = *(const ulonglong2*)(buf + k * 8 + 4);
            u64 xs[4] = {x01.x, x01.y, x23.x, x23.y};
#pragma unroll
            for (int p = 0; p < 4; p++) {
                u64 x = xs[p];
                t2a[p*3+0] = f2fma(M0,  x, t2a[p*3+0]);
                t2a[p*3+1] = f2fma(M1p, x, t2a[p*3+1]);
                t2a[p*3+2] = f2fma(M2p, x, t2a[p*3+2]);
            }
        }
    }
    reduceW(t2a);

    // ---- LN2 -> buf ----
    {
        float a[2][3], xn[2][3];
#pragma unroll
        for (int t = 0; t < 3; t++) up2(t2a[w*3+t], a[0][t], a[1][t]);
#pragma unroll
        for (int bb = 0; bb < 2; bb++) {
            float mu = warp_sum(a[bb][0] + a[bb][1] + a[bb][2]) * (1.0f/96.0f);
            float d0 = a[bb][0]-mu, d1 = a[bb][1]-mu, d2 = a[bb][2]-mu;
            float var = warp_sum(d0*d0 + d1*d1 + d2*d2) * (1.0f/96.0f);
            float rq = rsqrtf(var + 1e-5f);
            xn[bb][0] = fmaf(d0*rq, G2[0], B2[0]);
            xn[bb][1] = fmaf(d1*rq, G2[1], B2[1]);
            xn[bb][2] = fmaf(d2*rq, G2[2], B2[2]);
        }
        int bA = 2 * w;
#pragma unroll
        for (int bb = 0; bb < 2; bb++) {
            buf[i0*8 + bA+bb] = xn[bb][0];
            buf[i1*8 + bA+bb] = xn[bb][1];
            buf[i2*8 + bA+bb] = xn[bb][2];
        }
    }
    __syncthreads();

    // ---- W2 (j-quarter, from smem): oa partial ----
    u64 oa[12];
#pragma unroll
    for (int q = 0; q < 12; q++) oa[q] = 0ULL;
    wmat(sW2, oa);
    reduceW(oa);

    // ---- epilogue: out = oa + x1 (pack w only) ----
    {
        float v[2][3];
#pragma unroll
        for (int t = 0; t < 3; t++) {
            u64 r = f2add(oa[w*3+t], x1a[w*3+t]);
            up2(r, v[0][t], v[1][t]);
        }
        int bA = 2 * w;
#pragma unroll
        for (int bb = 0; bb < 2; bb++) {
            float* op = out + ((size_t)(bA+bb) * S_TOTAL + s) * Dm;
            op[i0] = v[bb][0];
            op[i1] = v[bb][1];
            op[i2] = v[bb][2];
        }
    }
}

#define LAYERS_SMEM (2 * JP * Dm * 4 + 12 * 4 * 32 * 8 + Din * 8 * 4 + Dm * 8 * 4)

extern "C" void kernel_launch(void* const* d_in, const int* in_sizes, int n_in,
                              void* d_out, int out_size) {
    const float* seq = (const float*)d_in[0];
    const float* M1  = (const float*)d_in[1];
    const float* P1  = (const float*)d_in[2];
    const float* Wr1 = (const float*)d_in[3];
    const float* g1  = (const float*)d_in[4];
    const float* b1  = (const float*)d_in[5];
    const float* M2  = (const float*)d_in[6];
    const float* P2  = (const float*)d_in[7];
    const float* g2  = (const float*)d_in[8];
    const float* b2  = (const float*)d_in[9];
    float* out = (float*)d_out;

    cudaFuncSetAttribute(layers_kernel,
                         cudaFuncAttributeMaxDynamicSharedMemorySize, LAYERS_SMEM);

    precompute_W<<<dim3(18, S_TOTAL / CHUNK, 2), 256>>>(P1, P2, M1, Wr1, M2);
    layers_kernel<<<dim3(S_TOTAL / 2, 2), 128, LAYERS_SMEM>>>(seq, g1, b1, g2, b2, out);
}